// round 5
// baseline (speedup 1.0000x reference)
#include <cuda_runtime.h>

// Problem shapes (fixed by the reference): P=2, E=256, H1=32, H2=16.
// B*N and M derived from in_sizes for robustness.
#define E_DIM 256
#define H1_DIM 32
#define H2_DIM 16

__global__ __launch_bounds__(256)
void rbf_fused_kernel(const float* __restrict__ z,     // [M, 2]
                      const float* __restrict__ mu,    // [BN, 2]
                      const float* __restrict__ emb,   // [BN, E]
                      const float* __restrict__ w1,    // [E, H1]
                      const float* __restrict__ b1,    // [H1]
                      const float* __restrict__ w2,    // [H1, H2]
                      const float* __restrict__ b2,    // [H2]
                      const float* __restrict__ w3,    // [H2, 1]
                      const float* __restrict__ b3,    // [1]
                      float* __restrict__ out,         // [BN, M]
                      int M)
{
    __shared__ float e_sh[E_DIM];
    __shared__ float coef_sh;   // -1 / (2 * sigma^2)

    const int row = blockIdx.x;
    const int t   = threadIdx.x;

    // Cooperative load of the embedding row (blockDim.x == E_DIM == 256).
    e_sh[t] = emb[(size_t)row * E_DIM + t];
    __syncthreads();

    // ---- Sigma MLP on warp 0 ----
    if (t < 32) {
        const float INV_SQRT2 = 0.70710678118654752f;

        // Layer 1: h1[t] = gelu(b1[t] + sum_k e[k] * w1[k][t])
        float acc = b1[t];
        #pragma unroll 8
        for (int k = 0; k < E_DIM; ++k) {
            acc = fmaf(e_sh[k], w1[k * H1_DIM + t], acc);
        }
        float h1 = 0.5f * acc * (1.0f + erff(acc * INV_SQRT2));

        // Layer 2: h2[j] = gelu(b2[j] + sum_i h1[i] * w2[i][j]), j in [0,16)
        float acc2 = (t < H2_DIM) ? b2[t] : 0.0f;
        #pragma unroll
        for (int i = 0; i < H1_DIM; ++i) {
            float v = __shfl_sync(0xffffffffu, h1, i);
            if (t < H2_DIM) acc2 = fmaf(v, w2[i * H2_DIM + t], acc2);
        }
        float h2 = 0.5f * acc2 * (1.0f + erff(acc2 * INV_SQRT2));

        // Layer 3 + sigmoid + sigma mapping (lane 0)
        float part = (t < H2_DIM) ? h2 * w3[t] : 0.0f;
        part += __shfl_down_sync(0xffffffffu, part, 8);
        part += __shfl_down_sync(0xffffffffu, part, 4);
        part += __shfl_down_sync(0xffffffffu, part, 2);
        part += __shfl_down_sync(0xffffffffu, part, 1);
        if (t == 0) {
            float s     = part + b3[0];
            float sig   = 1.0f / (1.0f + expf(-s));       // accurate expf: once per row
            float sigma = 0.1f + 9.9f * sig;              // MIN + (MAX-MIN)*sig
            coef_sh     = -0.5f / (sigma * sigma);
        }
    }
    __syncthreads();

    // ---- Streaming RBF phase: all 256 threads ----
    const float coef = coef_sh;
    const float mu0  = mu[row * 2 + 0];
    const float mu1  = mu[row * 2 + 1];

    const float4* __restrict__ z4   = (const float4*)z;            // 2 m's per float4
    float4* __restrict__       out4 = (float4*)out + (size_t)row * (M >> 2);
    const int nQuads = M >> 2;                                     // 4 m's per output float4

    for (int q = t; q < nQuads; q += 256) {
        float4 za = z4[2 * q];       // (z[4q].x, z[4q].y, z[4q+1].x, z[4q+1].y)
        float4 zb = z4[2 * q + 1];

        float d0x = za.x - mu0, d0y = za.y - mu1;
        float d1x = za.z - mu0, d1y = za.w - mu1;
        float d2x = zb.x - mu0, d2y = zb.y - mu1;
        float d3x = zb.z - mu0, d3y = zb.w - mu1;

        float4 o;
        o.x = __expf(coef * fmaf(d0x, d0x, d0y * d0y));
        o.y = __expf(coef * fmaf(d1x, d1x, d1y * d1y));
        o.z = __expf(coef * fmaf(d2x, d2x, d2y * d2y));
        o.w = __expf(coef * fmaf(d3x, d3x, d3y * d3y));
        out4[q] = o;
    }
}

extern "C" void kernel_launch(void* const* d_in, const int* in_sizes, int n_in,
                              void* d_out, int out_size)
{
    // metadata order: z, mu, embeddings, w1, b1, w2, b2, w3, b3
    const float* z   = (const float*)d_in[0];
    const float* mu  = (const float*)d_in[1];
    const float* emb = (const float*)d_in[2];
    const float* w1  = (const float*)d_in[3];
    const float* b1  = (const float*)d_in[4];
    const float* w2  = (const float*)d_in[5];
    const float* b2  = (const float*)d_in[6];
    const float* w3  = (const float*)d_in[7];
    const float* b3  = (const float*)d_in[8];
    float* out = (float*)d_out;

    const int M  = in_sizes[0] / 2;          // z is [M, 2]
    const int BN = in_sizes[2] / E_DIM;      // embeddings is [BN, E]

    rbf_fused_kernel<<<BN, 256>>>(z, mu, emb, w1, b1, w2, b2, w3, b3, out, M);
}

// round 6
// speedup vs baseline: 1.2254x; 1.2254x over previous
#include <cuda_runtime.h>

#define E_DIM 256
#define H1_DIM 32
#define H2_DIM 16
#define ROWS_PER_BLK 8
#define MAX_ROWS 32768

// Per-row precomputed exponent constants:
//   exponent(m) = a*r2[m] + k0*z0[m] + k1*z1[m] + c   (base-2, log2e folded in)
// where r2[m] = z0^2 + z1^2, a = -log2e/(2 sigma^2), k0 = -2 a mu0, etc.
__device__ float4 g_params[MAX_ROWS];

__device__ __forceinline__ float ex2(float x) {
    float y;
    asm("ex2.approx.f32 %0, %1;" : "=f"(y) : "f"(x));
    return y;
}

// ---------------- Kernel 1: sigma MLP, one warp per row ----------------
__global__ __launch_bounds__(256)
void sigma_kernel(const float* __restrict__ emb,   // [BN, E]
                  const float* __restrict__ mu,    // [BN, 2]
                  const float* __restrict__ w1,    // [E, H1]
                  const float* __restrict__ b1,
                  const float* __restrict__ w2,    // [H1, H2]
                  const float* __restrict__ b2,
                  const float* __restrict__ w3,    // [H2, 1]
                  const float* __restrict__ b3,
                  int BN)
{
    const int lane = threadIdx.x & 31;
    const int row  = blockIdx.x * 8 + (threadIdx.x >> 5);
    if (row >= BN) return;

    // Embedding row into registers: lane holds e[lane + 32*j]
    float e[8];
    const float* er = emb + (size_t)row * E_DIM;
    #pragma unroll
    for (int j = 0; j < 8; ++j) e[j] = er[lane + 32 * j];

    const float INV_SQRT2 = 0.70710678118654752f;

    // Layer 1: h1[lane] = gelu(b1 + sum_k e[k] * w1[k][lane])
    float acc = b1[lane];
    #pragma unroll
    for (int j = 0; j < 8; ++j) {
        #pragma unroll
        for (int i = 0; i < 32; ++i) {
            float v = __shfl_sync(0xffffffffu, e[j], i);
            acc = fmaf(v, __ldg(&w1[(j * 32 + i) * H1_DIM + lane]), acc);
        }
    }
    float h1 = 0.5f * acc * (1.0f + erff(acc * INV_SQRT2));

    // Layer 2 (j in [0,16))
    float acc2 = (lane < H2_DIM) ? b2[lane] : 0.0f;
    #pragma unroll
    for (int i = 0; i < H1_DIM; ++i) {
        float v = __shfl_sync(0xffffffffu, h1, i);
        if (lane < H2_DIM) acc2 = fmaf(v, __ldg(&w2[i * H2_DIM + lane]), acc2);
    }
    float h2 = 0.5f * acc2 * (1.0f + erff(acc2 * INV_SQRT2));

    // Layer 3 + sigmoid + sigma map
    float part = (lane < H2_DIM) ? h2 * __ldg(&w3[lane]) : 0.0f;
    part += __shfl_down_sync(0xffffffffu, part, 8);
    part += __shfl_down_sync(0xffffffffu, part, 4);
    part += __shfl_down_sync(0xffffffffu, part, 2);
    part += __shfl_down_sync(0xffffffffu, part, 1);
    if (lane == 0) {
        float s     = part + b3[0];
        float sig   = 1.0f / (1.0f + expf(-s));   // accurate; once per row
        float sigma = 0.1f + 9.9f * sig;
        const float LOG2E = 1.4426950408889634f;
        float a  = -0.5f * LOG2E / (sigma * sigma);
        float m0 = mu[row * 2 + 0];
        float m1 = mu[row * 2 + 1];
        g_params[row] = make_float4(a,
                                    -2.0f * a * m0,
                                    -2.0f * a * m1,
                                    a * fmaf(m0, m0, m1 * m1));
    }
}

// ---------------- Kernel 2: streaming RBF, 8 rows per block ----------------
// Thread owns one m-quad; z and r2 live in registers across all 8 rows.
__global__ __launch_bounds__(512)
void rbf_stream_kernel(const float* __restrict__ z,   // [M, 2]
                       float* __restrict__ out,       // [BN, M]
                       int M, int BN)
{
    __shared__ float4 p_sh[ROWS_PER_BLK];

    const int rowBase = blockIdx.x * ROWS_PER_BLK;
    const int nRows   = min(ROWS_PER_BLK, BN - rowBase);
    const int nQuads  = M >> 2;

    if (threadIdx.x < (unsigned)nRows)
        p_sh[threadIdx.x] = g_params[rowBase + threadIdx.x];
    __syncthreads();

    const float4* __restrict__ z4 = (const float4*)z;

    for (int q = threadIdx.x; q < nQuads; q += blockDim.x) {
        float4 za = z4[2 * q];        // (z0,z1) of m=4q, 4q+1
        float4 zb = z4[2 * q + 1];    // (z0,z1) of m=4q+2, 4q+3

        float r0 = fmaf(za.x, za.x, za.y * za.y);
        float r1 = fmaf(za.z, za.z, za.w * za.w);
        float r2 = fmaf(zb.x, zb.x, zb.y * zb.y);
        float r3 = fmaf(zb.z, zb.z, zb.w * zb.w);

        float4* out4 = (float4*)out + (size_t)rowBase * nQuads + q;

        #pragma unroll
        for (int r = 0; r < ROWS_PER_BLK; ++r) {
            if (r >= nRows) break;
            float4 p = p_sh[r];
            float4 o;
            o.x = ex2(fmaf(p.x, r0, fmaf(p.y, za.x, fmaf(p.z, za.y, p.w))));
            o.y = ex2(fmaf(p.x, r1, fmaf(p.y, za.z, fmaf(p.z, za.w, p.w))));
            o.z = ex2(fmaf(p.x, r2, fmaf(p.y, zb.x, fmaf(p.z, zb.y, p.w))));
            o.w = ex2(fmaf(p.x, r3, fmaf(p.y, zb.z, fmaf(p.z, zb.w, p.w))));
            out4[(size_t)r * nQuads] = o;
        }
    }
}

extern "C" void kernel_launch(void* const* d_in, const int* in_sizes, int n_in,
                              void* d_out, int out_size)
{
    // metadata order: z, mu, embeddings, w1, b1, w2, b2, w3, b3
    const float* z   = (const float*)d_in[0];
    const float* mu  = (const float*)d_in[1];
    const float* emb = (const float*)d_in[2];
    const float* w1  = (const float*)d_in[3];
    const float* b1  = (const float*)d_in[4];
    const float* w2  = (const float*)d_in[5];
    const float* b2  = (const float*)d_in[6];
    const float* w3  = (const float*)d_in[7];
    const float* b3  = (const float*)d_in[8];
    float* out = (float*)d_out;

    const int M  = in_sizes[0] / 2;      // z is [M, 2]
    const int BN = in_sizes[2] / E_DIM;  // embeddings is [BN, E]

    const int sigmaBlocks = (BN + 7) / 8;
    sigma_kernel<<<sigmaBlocks, 256>>>(emb, mu, w1, b1, w2, b2, w3, b3, BN);

    const int streamBlocks = (BN + ROWS_PER_BLK - 1) / ROWS_PER_BLK;
    rbf_stream_kernel<<<streamBlocks, 512>>>(z, out, M, BN);
}

// round 7
// speedup vs baseline: 1.3811x; 1.1270x over previous
#include <cuda_runtime.h>

#define E_DIM 256
#define H1_DIM 32
#define H2_DIM 16
#define SROWS 8            // sigma kernel: rows per block (warp per row)
#define ROWS_PER_BLK 16    // stream kernel: rows per block
#define MAX_ROWS 32768

// Per-row precomputed exponent constants (base-2, log2e folded in):
//   exponent(m) = a*r2[m] + k0*z0[m] + k1*z1[m] + c,  r2 = z0^2 + z1^2
__device__ float4 g_params[MAX_ROWS];

__device__ __forceinline__ float ex2(float x) {
    float y;
    asm("ex2.approx.f32 %0, %1;" : "=f"(y) : "f"(x));
    return y;
}

__device__ __forceinline__ float gelu_exact(float x) {
    const float INV_SQRT2 = 0.70710678118654752f;
    return 0.5f * x * (1.0f + erff(x * INV_SQRT2));
}

// ---------------- Kernel 1: sigma MLP, warp per row, shuffle-free layer 1 ----
__global__ __launch_bounds__(256)
void sigma_kernel(const float* __restrict__ emb,   // [BN, E]
                  const float* __restrict__ mu,    // [BN, 2]
                  const float* __restrict__ w1,    // [E, H1]
                  const float* __restrict__ b1,    // [H1]
                  const float* __restrict__ w2,    // [H1, H2]
                  const float* __restrict__ b2,    // [H2]
                  const float* __restrict__ w3,    // [H2, 1]
                  const float* __restrict__ b3,    // [1]
                  int BN)
{
    __shared__ float e_sh[SROWS][E_DIM];       // 8 KB
    __shared__ float h1_sh[SROWS][H1_DIM];     // 1 KB
    __shared__ float w2_sh[H1_DIM * H2_DIM];   // 2 KB
    __shared__ float w3_sh[H2_DIM];

    const int warp = threadIdx.x >> 5;
    const int lane = threadIdx.x & 31;
    const int row  = blockIdx.x * SROWS + warp;

    // Cooperative load of SROWS embedding rows (float4: SROWS*64 = 512 loads, 2/thread)
    {
        const float4* embv = (const float4*)emb;
        const size_t base = (size_t)blockIdx.x * SROWS * (E_DIM / 4);
        const size_t limit = (size_t)BN * (E_DIM / 4);
        float4* esv = (float4*)&e_sh[0][0];
        #pragma unroll
        for (int i = 0; i < SROWS * (E_DIM / 4) / 256; ++i) {
            int idx = threadIdx.x + i * 256;
            if (base + idx < limit) esv[idx] = embv[base + idx];
        }
    }
    // Preload small weights
    if (threadIdx.x < H1_DIM * H2_DIM / 2) {
        w2_sh[threadIdx.x * 2 + 0] = w2[threadIdx.x * 2 + 0];
        w2_sh[threadIdx.x * 2 + 1] = w2[threadIdx.x * 2 + 1];
    }
    if (threadIdx.x < H2_DIM) w3_sh[threadIdx.x] = w3[threadIdx.x];
    __syncthreads();

    if (row >= BN) return;

    // ---- Layer 1: group g handles k = 4*kk + g; sub owns h = 4*sub..4*sub+3 ----
    const int g   = lane >> 3;   // 0..3
    const int sub = lane & 7;    // 0..7
    float ax = 0.f, ay = 0.f, az = 0.f, aw = 0.f;
    #pragma unroll 16
    for (int kk = 0; kk < E_DIM / 4; ++kk) {
        const int k = kk * 4 + g;
        const float ev = e_sh[warp][k];                       // broadcast LDS
        const float4 w = __ldg((const float4*)&w1[k * H1_DIM + sub * 4]);
        ax = fmaf(ev, w.x, ax);
        ay = fmaf(ev, w.y, ay);
        az = fmaf(ev, w.z, az);
        aw = fmaf(ev, w.w, aw);
    }
    // Reduce across the 4 lane-groups (lanes sub, sub+8, sub+16, sub+24)
    ax += __shfl_xor_sync(0xffffffffu, ax, 8);
    ay += __shfl_xor_sync(0xffffffffu, ay, 8);
    az += __shfl_xor_sync(0xffffffffu, az, 8);
    aw += __shfl_xor_sync(0xffffffffu, aw, 8);
    ax += __shfl_xor_sync(0xffffffffu, ax, 16);
    ay += __shfl_xor_sync(0xffffffffu, ay, 16);
    az += __shfl_xor_sync(0xffffffffu, az, 16);
    aw += __shfl_xor_sync(0xffffffffu, aw, 16);

    if (lane < 8) {
        const float4 bb = __ldg((const float4*)&b1[lane * 4]);
        h1_sh[warp][lane * 4 + 0] = gelu_exact(ax + bb.x);
        h1_sh[warp][lane * 4 + 1] = gelu_exact(ay + bb.y);
        h1_sh[warp][lane * 4 + 2] = gelu_exact(az + bb.z);
        h1_sh[warp][lane * 4 + 3] = gelu_exact(aw + bb.w);
    }
    __syncwarp();

    // ---- Layer 2 (lanes 0..15) + layer 3 reduction ----
    float part = 0.0f;
    if (lane < H2_DIM) {
        float acc2 = __ldg(&b2[lane]);
        #pragma unroll
        for (int i = 0; i < H1_DIM; ++i)
            acc2 = fmaf(h1_sh[warp][i], w2_sh[i * H2_DIM + lane], acc2);
        part = gelu_exact(acc2) * w3_sh[lane];
    }
    part += __shfl_down_sync(0xffffffffu, part, 8);
    part += __shfl_down_sync(0xffffffffu, part, 4);
    part += __shfl_down_sync(0xffffffffu, part, 2);
    part += __shfl_down_sync(0xffffffffu, part, 1);

    if (lane == 0) {
        float s     = part + __ldg(&b3[0]);
        float sig   = 1.0f / (1.0f + expf(-s));   // accurate; once per row
        float sigma = 0.1f + 9.9f * sig;
        const float LOG2E = 1.4426950408889634f;
        float a  = -0.5f * LOG2E / (sigma * sigma);
        float m0 = mu[row * 2 + 0];
        float m1 = mu[row * 2 + 1];
        g_params[row] = make_float4(a,
                                    -2.0f * a * m0,
                                    -2.0f * a * m1,
                                    a * fmaf(m0, m0, m1 * m1));
    }
}

// ---------------- Kernel 2: streaming RBF, 16 rows per block ----------------
__global__ __launch_bounds__(512)
void rbf_stream_kernel(const float* __restrict__ z,   // [M, 2]
                       float* __restrict__ out,       // [BN, M]
                       int M, int BN)
{
    __shared__ float4 p_sh[ROWS_PER_BLK];

    const int rowBase = blockIdx.x * ROWS_PER_BLK;
    const int nRows   = min(ROWS_PER_BLK, BN - rowBase);
    const int nQuads  = M >> 2;

    if (threadIdx.x < (unsigned)nRows)
        p_sh[threadIdx.x] = g_params[rowBase + threadIdx.x];
    __syncthreads();

    const float4* __restrict__ z4 = (const float4*)z;

    for (int q = threadIdx.x; q < nQuads; q += blockDim.x) {
        float4 za = z4[2 * q];        // (z0,z1) of m=4q, 4q+1
        float4 zb = z4[2 * q + 1];    // (z0,z1) of m=4q+2, 4q+3

        float r0 = fmaf(za.x, za.x, za.y * za.y);
        float r1 = fmaf(za.z, za.z, za.w * za.w);
        float r2 = fmaf(zb.x, zb.x, zb.y * zb.y);
        float r3 = fmaf(zb.z, zb.z, zb.w * zb.w);

        float4* out4 = (float4*)out + (size_t)rowBase * nQuads + q;

        #pragma unroll
        for (int r = 0; r < ROWS_PER_BLK; ++r) {
            if (r >= nRows) break;
            float4 p = p_sh[r];
            float4 o;
            o.x = ex2(fmaf(p.x, r0, fmaf(p.y, za.x, fmaf(p.z, za.y, p.w))));
            o.y = ex2(fmaf(p.x, r1, fmaf(p.y, za.z, fmaf(p.z, za.w, p.w))));
            o.z = ex2(fmaf(p.x, r2, fmaf(p.y, zb.x, fmaf(p.z, zb.y, p.w))));
            o.w = ex2(fmaf(p.x, r3, fmaf(p.y, zb.z, fmaf(p.z, zb.w, p.w))));
            out4[(size_t)r * nQuads] = o;
        }
    }
}

extern "C" void kernel_launch(void* const* d_in, const int* in_sizes, int n_in,
                              void* d_out, int out_size)
{
    // metadata order: z, mu, embeddings, w1, b1, w2, b2, w3, b3
    const float* z   = (const float*)d_in[0];
    const float* mu  = (const float*)d_in[1];
    const float* emb = (const float*)d_in[2];
    const float* w1  = (const float*)d_in[3];
    const float* b1  = (const float*)d_in[4];
    const float* w2  = (const float*)d_in[5];
    const float* b2  = (const float*)d_in[6];
    const float* w3  = (const float*)d_in[7];
    const float* b3  = (const float*)d_in[8];
    float* out = (float*)d_out;

    const int M  = in_sizes[0] / 2;      // z is [M, 2]
    const int BN = in_sizes[2] / E_DIM;  // embeddings is [BN, E]

    const int sigmaBlocks = (BN + SROWS - 1) / SROWS;
    sigma_kernel<<<sigmaBlocks, 256>>>(emb, mu, w1, b1, w2, b2, w3, b3, BN);

    const int streamBlocks = (BN + ROWS_PER_BLK - 1) / ROWS_PER_BLK;
    rbf_stream_kernel<<<streamBlocks, 512>>>(z, out, M, BN);
}

// round 8
// speedup vs baseline: 1.4918x; 1.0801x over previous
#include <cuda_runtime.h>

#define E_DIM 256
#define H1 32
#define H2 16
#define SIG_WARPS 2
#define SIG_ROWS 32          // rows per sigma block (16 per warp)
#define EPAD 260             // padded e row stride (words) to dodge bank conflicts
#define ROWS_PER_BLK 8       // stream kernel rows per block
#define MAX_ROWS 32768

// Per-row precomputed exponent constants (base-2, log2e folded in):
//   exponent(m) = a*r2[m] + k0*z0[m] + k1*z1[m] + c,  r2 = z0^2+z1^2
__device__ float4 g_params[MAX_ROWS];

__device__ __forceinline__ float ex2f(float x) {
    float y;
    asm("ex2.approx.f32 %0, %1;" : "=f"(y) : "f"(x));
    return y;
}
__device__ __forceinline__ float gelu_exact(float x) {
    return 0.5f * x * (1.0f + erff(x * 0.70710678118654752f));
}

// ---------------- Kernel 1: sigma MLP ----------------
// 64 threads/block, 32 rows/block. Warp owns 16 rows; lane = (r, p):
// r = lane>>1 selects row, p = lane&1 selects h-half (h = p*16..p*16+15).
// All k processed by every lane; w1 reads are warp-broadcast LDS.
extern __shared__ float smem_dyn[];

__global__ void sigma_kernel(const float* __restrict__ emb,   // [BN, E]
                             const float* __restrict__ mu,    // [BN, 2]
                             const float* __restrict__ w1,    // [E, H1]
                             const float* __restrict__ b1,
                             const float* __restrict__ w2,    // [H1, H2]
                             const float* __restrict__ b2,
                             const float* __restrict__ w3,    // [H2, 1]
                             const float* __restrict__ b3,
                             int BN)
{
    float* w1_sh = smem_dyn;                  // 256*32 floats = 32 KB
    float* e_sh  = smem_dyn + E_DIM * H1;     // 2 warps * 16 rows * EPAD

    const int tid  = threadIdx.x;
    const int warp = tid >> 5;
    const int lane = tid & 31;
    const int rowBase = blockIdx.x * SIG_ROWS;

    // Stage w1 (coalesced, 2048 float4 / 64 threads = 32 iters)
    {
        const float4* s = (const float4*)w1;
        float4* d = (float4*)w1_sh;
        #pragma unroll
        for (int i = 0; i < (E_DIM * H1 / 4) / 64; ++i)
            d[tid + i * 64] = s[tid + i * 64];
    }
    // Stage e tile: 32 rows * 256 floats (coalesced src, padded dst)
    {
        const float4* s = (const float4*)emb + (size_t)rowBase * (E_DIM / 4);
        const size_t base = (size_t)rowBase * (E_DIM / 4);
        const size_t lim  = (size_t)BN * (E_DIM / 4);
        #pragma unroll
        for (int i = 0; i < (SIG_ROWS * E_DIM / 4) / 64; ++i) {
            int idx = tid + i * 64;        // 0..2047
            int rr  = idx >> 6;            // local row 0..31
            int cc  = idx & 63;            // float4 col
            float4 v = (base + idx < lim) ? s[idx] : make_float4(0, 0, 0, 0);
            *(float4*)&e_sh[(rr >> 4) * 16 * EPAD + (rr & 15) * EPAD + cc * 4] = v;
        }
    }
    __syncthreads();

    const float* my_e  = e_sh + warp * 16 * EPAD;
    const int r = lane >> 1;
    const int p = lane & 1;
    const float* wbase = w1_sh + p * 16;      // this lane's h-half

    // ---- Layer 1: packed f32x2 accumulation, 16 h per lane ----
    unsigned long long acc[8];
    #pragma unroll
    for (int i = 0; i < 8; ++i) acc[i] = 0ULL;

    #pragma unroll 4
    for (int c = 0; c < 64; ++c) {            // float4 chunks over k
        const float4 ev = *(const float4*)&my_e[r * EPAD + c * 4];
        #pragma unroll
        for (int j = 0; j < 4; ++j) {
            const float ek = (j == 0) ? ev.x : (j == 1) ? ev.y : (j == 2) ? ev.z : ev.w;
            unsigned long long ekk;
            asm("mov.b64 %0, {%1, %1};" : "=l"(ekk) : "f"(ek));
            const int k = c * 4 + j;
            const ulonglong2* wr = (const ulonglong2*)(wbase + k * H1);
            #pragma unroll
            for (int q = 0; q < 4; ++q) {     // 4 x 16B = my 16 h floats
                const ulonglong2 w = wr[q];   // broadcast LDS.128
                asm("fma.rn.f32x2 %0, %1, %2, %0;" : "+l"(acc[q * 2 + 0]) : "l"(ekk), "l"(w.x));
                asm("fma.rn.f32x2 %0, %1, %2, %0;" : "+l"(acc[q * 2 + 1]) : "l"(ekk), "l"(w.y));
            }
        }
    }

    // Unpack + bias + GELU: lane owns h = p*16 + 0..15
    float h1v[16];
    #pragma unroll
    for (int q = 0; q < 8; ++q) {
        float lo, hi;
        asm("mov.b64 {%0, %1}, %2;" : "=f"(lo), "=f"(hi) : "l"(acc[q]));
        const int h = p * 16 + q * 2;
        h1v[q * 2 + 0] = gelu_exact(lo + __ldg(&b1[h]));
        h1v[q * 2 + 1] = gelu_exact(hi + __ldg(&b1[h + 1]));
    }

    // ---- Layer 2: partial over my 16 i's for all 16 j ----
    float acc2[16];
    #pragma unroll
    for (int j = 0; j < 16; ++j) acc2[j] = 0.0f;
    #pragma unroll
    for (int ii = 0; ii < 16; ++ii) {
        const int i = p * 16 + ii;
        const float hv = h1v[ii];
        const float4* w2r = (const float4*)(w2 + i * H2);
        #pragma unroll
        for (int jq = 0; jq < 4; ++jq) {
            const float4 w = __ldg(&w2r[jq]);
            acc2[jq * 4 + 0] = fmaf(hv, w.x, acc2[jq * 4 + 0]);
            acc2[jq * 4 + 1] = fmaf(hv, w.y, acc2[jq * 4 + 1]);
            acc2[jq * 4 + 2] = fmaf(hv, w.z, acc2[jq * 4 + 2]);
            acc2[jq * 4 + 3] = fmaf(hv, w.w, acc2[jq * 4 + 3]);
        }
    }
    // Combine the two h-half partials (partner lane differs only in p)
    #pragma unroll
    for (int j = 0; j < 16; ++j)
        acc2[j] += __shfl_xor_sync(0xffffffffu, acc2[j], 1);

    // ---- Layer 3: each lane GELUs 8 j's and dots with w3 ----
    float part = 0.0f;
    #pragma unroll
    for (int jj = 0; jj < 8; ++jj) {
        const int j = p * 8 + jj;
        const float h2v = gelu_exact(acc2[j] + __ldg(&b2[j]));
        part = fmaf(h2v, __ldg(&w3[j]), part);
    }
    part += __shfl_xor_sync(0xffffffffu, part, 1);

    const int row = rowBase + warp * 16 + r;
    if (p == 0 && row < BN) {
        const float s     = part + __ldg(&b3[0]);
        const float sig   = 1.0f / (1.0f + expf(-s));   // accurate, once/row
        const float sigma = 0.1f + 9.9f * sig;
        const float LOG2E = 1.4426950408889634f;
        const float a  = -0.5f * LOG2E / (sigma * sigma);
        const float m0 = mu[row * 2 + 0];
        const float m1 = mu[row * 2 + 1];
        g_params[row] = make_float4(a, -2.0f * a * m0, -2.0f * a * m1,
                                    a * fmaf(m0, m0, m1 * m1));
    }
}

// ---------------- Kernel 2: streaming RBF, 8 rows per block ----------------
__global__ __launch_bounds__(512)
void rbf_stream_kernel(const float* __restrict__ z,   // [M, 2]
                       float* __restrict__ out,       // [BN, M]
                       int M, int BN)
{
    __shared__ float4 p_sh[ROWS_PER_BLK];

    const int rowBase = blockIdx.x * ROWS_PER_BLK;
    const int nQuads  = M >> 2;

    if (threadIdx.x < ROWS_PER_BLK) {
        const int rr = rowBase + threadIdx.x;
        p_sh[threadIdx.x] = (rr < BN) ? g_params[rr] : make_float4(0, 0, 0, 0);
    }
    __syncthreads();

    const float4* __restrict__ z4 = (const float4*)z;
    const int nRows = min(ROWS_PER_BLK, BN - rowBase);

    for (int q = threadIdx.x; q < nQuads; q += blockDim.x) {
        const float4 za = z4[2 * q];
        const float4 zb = z4[2 * q + 1];

        const float r0 = fmaf(za.x, za.x, za.y * za.y);
        const float r1 = fmaf(za.z, za.z, za.w * za.w);
        const float r2 = fmaf(zb.x, zb.x, zb.y * zb.y);
        const float r3 = fmaf(zb.z, zb.z, zb.w * zb.w);

        float4* out4 = (float4*)out + (size_t)rowBase * nQuads + q;

        if (nRows == ROWS_PER_BLK) {
            #pragma unroll
            for (int r = 0; r < ROWS_PER_BLK; ++r) {
                const float4 p = p_sh[r];
                float4 o;
                o.x = ex2f(fmaf(p.x, r0, fmaf(p.y, za.x, fmaf(p.z, za.y, p.w))));
                o.y = ex2f(fmaf(p.x, r1, fmaf(p.y, za.z, fmaf(p.z, za.w, p.w))));
                o.z = ex2f(fmaf(p.x, r2, fmaf(p.y, zb.x, fmaf(p.z, zb.y, p.w))));
                o.w = ex2f(fmaf(p.x, r3, fmaf(p.y, zb.z, fmaf(p.z, zb.w, p.w))));
                out4[(size_t)r * nQuads] = o;
            }
        } else {
            for (int r = 0; r < nRows; ++r) {
                const float4 p = p_sh[r];
                float4 o;
                o.x = ex2f(fmaf(p.x, r0, fmaf(p.y, za.x, fmaf(p.z, za.y, p.w))));
                o.y = ex2f(fmaf(p.x, r1, fmaf(p.y, za.z, fmaf(p.z, za.w, p.w))));
                o.z = ex2f(fmaf(p.x, r2, fmaf(p.y, zb.x, fmaf(p.z, zb.y, p.w))));
                o.w = ex2f(fmaf(p.x, r3, fmaf(p.y, zb.z, fmaf(p.z, zb.w, p.w))));
                out4[(size_t)r * nQuads] = o;
            }
        }
    }
}

extern "C" void kernel_launch(void* const* d_in, const int* in_sizes, int n_in,
                              void* d_out, int out_size)
{
    // metadata order: z, mu, embeddings, w1, b1, w2, b2, w3, b3
    const float* z   = (const float*)d_in[0];
    const float* mu  = (const float*)d_in[1];
    const float* emb = (const float*)d_in[2];
    const float* w1  = (const float*)d_in[3];
    const float* b1  = (const float*)d_in[4];
    const float* w2  = (const float*)d_in[5];
    const float* b2  = (const float*)d_in[6];
    const float* w3  = (const float*)d_in[7];
    const float* b3  = (const float*)d_in[8];
    float* out = (float*)d_out;

    const int M  = in_sizes[0] / 2;      // z is [M, 2]
    const int BN = in_sizes[2] / E_DIM;  // embeddings is [BN, E]

    const int sigSmem = (E_DIM * H1 + SIG_WARPS * 16 * EPAD) * (int)sizeof(float); // ~66 KB
    static bool attrSet = false;
    if (!attrSet) {
        cudaFuncSetAttribute(sigma_kernel, cudaFuncAttributeMaxDynamicSharedMemorySize, sigSmem);
        attrSet = true;
    }

    const int sigmaBlocks = (BN + SIG_ROWS - 1) / SIG_ROWS;
    sigma_kernel<<<sigmaBlocks, 64, sigSmem>>>(emb, mu, w1, b1, w2, b2, w3, b3, BN);

    const int streamBlocks = (BN + ROWS_PER_BLK - 1) / ROWS_PER_BLK;
    rbf_stream_kernel<<<streamBlocks, 512>>>(z, out, M, BN);
}